// round 15
// baseline (speedup 1.0000x reference)
#include <cuda_runtime.h>
#include <mma.h>

namespace wm = nvcuda::wmma;

#define MAXA 400000
#define MAXT 100000

// ---------------- device scratch ---------------------------------------------
__device__ float g_exp[MAXA];
__device__ float g_denom[MAXT];
__device__ int   g_count[MAXT];
__device__ int   g_offs[MAXT];
__device__ int   g_cursor[MAXT];
__device__ int2  g_pair[MAXA];
__device__ int   g_bsum[256];
__device__ int   g_idxflag;
__device__ float g_teamh[MAXT * 256];

__device__ __forceinline__ int team_of(const void* ti, int a, int f64) {
    return f64 ? (int)((const long long*)ti)[a] : ((const int*)ti)[a];
}
__device__ __forceinline__ float fast_tanh(float x) {
    float y; asm("tanh.approx.f32 %0, %1;" : "=f"(y) : "f"(x)); return y;
}
__device__ __forceinline__ float fast_exp(float x) {
    float y; asm("ex2.approx.f32 %0, %1;" : "=f"(y) : "f"(x * 1.4426950408889634f));
    return y;
}

// ---------------- smem layout for both GEMMs ----------------------------------
// ring: 4 slots x (128 rows x 68 floats)  = 34816 floats
// Hs:   128 x 132                          = 16896 floats
// bias: 2 x 128
#define CHUNK_LD 68
#define SLOT_FLOATS (128 * CHUNK_LD)
#define HS_LD 132
#define SM_FLOATS (4 * SLOT_FLOATS + 128 * HS_LD + 256)
#define SM_BYTES  (SM_FLOATS * 4)

// ---------------- init kernels -------------------------------------------------
__global__ void k_detect(const void* __restrict__ ti, int nA, int nT) {
    if (blockIdx.x == 0 && threadIdx.x < 32) {
        const long long* p = (const long long*)ti;
        int n = nA < 64 ? nA : 64;
        bool bad = false;
        for (int j = threadIdx.x; j < n; j += 32) {
            long long v = p[j];
            if (v < 0 || v >= (long long)nT) bad = true;
        }
        unsigned m = __ballot_sync(0xffffffffu, bad);
        if (threadIdx.x == 0) g_idxflag = (m == 0) ? 1 : 0;
    }
}
__global__ void k_clearA(int nT) {
    int i = blockIdx.x * blockDim.x + threadIdx.x;
    if (i < nT) { g_denom[i] = 0.f; g_count[i] = 0; }
}
__global__ void k_clearB(int nT) {
    int i = blockIdx.x * blockDim.x + threadIdx.x;
    if (i < nT) g_cursor[i] = 0;
}

// ---------------- GEMM1: g_exp = exp(tanh(A@W1+b1)@W2 + b2) -------------------
__global__ void __launch_bounds__(256, 1)
k_gemm1(const float* __restrict__ A, const float* __restrict__ W1,
        const float* __restrict__ b1, const float* __restrict__ W2,
        const float* __restrict__ b2p, int nA)
{
    extern __shared__ float sm[];
    float* ring = sm;
    float* Hs   = sm + 4 * SLOT_FLOATS;
    float* b1s  = Hs + 128 * HS_LD;
    float* W2s  = b1s + 128;
    const int tid = threadIdx.x, warp = tid >> 5, lane = tid & 31;

    if (tid < 128) { b1s[tid] = b1[tid]; W2s[tid] = W2[tid]; }

    // preload W1 -> register B fragments (two 128-row passes through Hs)
    wm::fragment<wm::matrix_b, 16, 16, 8, wm::precision::tf32, wm::row_major> bfr[32];
    for (int pass = 0; pass < 2; pass++) {
        __syncthreads();
        for (int i = tid; i < 4096; i += 256) {
            int r = i >> 5, c4 = i & 31;
            float4 v = ((const float4*)W1)[pass * 4096 + i];
            float* d = &Hs[r * HS_LD + c4 * 4];
            d[0] = wm::__float_to_tf32(v.x); d[1] = wm::__float_to_tf32(v.y);
            d[2] = wm::__float_to_tf32(v.z); d[3] = wm::__float_to_tf32(v.w);
        }
        __syncthreads();
        #pragma unroll
        for (int kk = 0; kk < 16; kk++)
            wm::load_matrix_sync(bfr[pass * 16 + kk], &Hs[(kk * 8) * HS_LD + warp * 16], HS_LD);
    }
    const float b2 = b2p[0];

    const int ntiles = (nA + 127) >> 7;
    int myT = ((int)blockIdx.x < ntiles)
            ? (ntiles - (int)blockIdx.x + (int)gridDim.x - 1) / (int)gridDim.x : 0;
    const int totQ = myT * 4;

    auto stage = [&](int q) {
        if (q < totQ) {
            int ti = (int)blockIdx.x + (q >> 2) * (int)gridDim.x;
            int c  = q & 3;
            int row0 = ti << 7;
            float* dst = ring + (q & 3) * SLOT_FLOATS;
            for (int i = tid; i < 2048; i += 256) {
                int r = i >> 4, grp = i & 15;
                int g = row0 + r;
                int ok = (g < nA);
                int sz = ok ? 16 : 0;
                const float* s = A + (size_t)(ok ? g : 0) * 256 + c * 64 + grp * 4;
                unsigned da = (unsigned)__cvta_generic_to_shared(&dst[r * CHUNK_LD + grp * 4]);
                asm volatile("cp.async.cg.shared.global [%0], [%1], 16, %2;\n"
                             :: "r"(da), "l"(s), "r"(sz));
            }
        }
        asm volatile("cp.async.commit_group;\n");
    };

    wm::fragment<wm::accumulator, 16, 16, 8, float> acc[8];
    #pragma unroll
    for (int m = 0; m < 8; m++) wm::fill_fragment(acc[m], 0.f);

    stage(0); stage(1); stage(2);
    for (int q = 0; q < totQ; q++) {
        asm volatile("cp.async.wait_group 2;\n");
        __syncthreads();
        float* slot = ring + (q & 3) * SLOT_FLOATS;
        const int kb = (q & 3) * 8;
        #pragma unroll
        for (int k8 = 0; k8 < 8; k8++) {
            #pragma unroll
            for (int m = 0; m < 8; m++) {
                wm::fragment<wm::matrix_a, 16, 16, 8, wm::precision::tf32, wm::row_major> af;
                wm::load_matrix_sync(af, &slot[(m * 16) * CHUNK_LD + k8 * 8], CHUNK_LD);
                wm::mma_sync(acc[m], af, bfr[kb + k8], acc[m]);
            }
        }
        stage(q + 3);
        if ((q & 3) == 3) {
            #pragma unroll
            for (int m = 0; m < 8; m++) {
                wm::store_matrix_sync(&Hs[(m * 16) * HS_LD + warp * 16], acc[m], HS_LD,
                                      wm::mem_row_major);
                wm::fill_fragment(acc[m], 0.f);
            }
            __syncthreads();
            const int row0 = ((int)blockIdx.x + (q >> 2) * (int)gridDim.x) << 7;
            #pragma unroll
            for (int rr = 0; rr < 16; rr++) {
                int r = warp * 16 + rr;
                int c = lane * 4;
                float4 h = *(const float4*)&Hs[r * HS_LD + c];
                float s = fast_tanh(h.x + b1s[c])     * W2s[c]
                        + fast_tanh(h.y + b1s[c + 1]) * W2s[c + 1]
                        + fast_tanh(h.z + b1s[c + 2]) * W2s[c + 2]
                        + fast_tanh(h.w + b1s[c + 3]) * W2s[c + 3];
                #pragma unroll
                for (int o = 16; o > 0; o >>= 1) s += __shfl_xor_sync(0xffffffffu, s, o);
                int g = row0 + r;
                if (lane == 0 && g < nA) g_exp[g] = fast_exp(s + b2);
            }
        }
    }
}

// ---------------- denom + count (separate: off the GEMM critical path) --------
__global__ void k_accum(const void* __restrict__ ti, int nA) {
    int a = blockIdx.x * blockDim.x + threadIdx.x;
    if (a >= nA) return;
    int t = team_of(ti, a, g_idxflag);
    atomicAdd(&g_denom[t], g_exp[a]);
    atomicAdd(&g_count[t], 1);
}

// ---------------- scan (counts -> offsets) --------------------------------------
__global__ void k_scan1(int nT) {
    __shared__ int ws[32];
    int i = blockIdx.x * 1024 + threadIdx.x;
    int lane = threadIdx.x & 31, wid = threadIdx.x >> 5;
    int v = (i < nT) ? g_count[i] : 0;
    int inc = v;
    #pragma unroll
    for (int o = 1; o < 32; o <<= 1) {
        int n = __shfl_up_sync(0xffffffffu, inc, o);
        if (lane >= o) inc += n;
    }
    if (lane == 31) ws[wid] = inc;
    __syncthreads();
    if (wid == 0) {
        int tt = ws[lane];
        #pragma unroll
        for (int o = 1; o < 32; o <<= 1) {
            int n = __shfl_up_sync(0xffffffffu, tt, o);
            if (lane >= o) tt += n;
        }
        ws[lane] = tt;
    }
    __syncthreads();
    int warpPre = wid ? ws[wid - 1] : 0;
    if (i < nT) g_offs[i] = warpPre + inc - v;
    if (threadIdx.x == 1023) g_bsum[blockIdx.x] = warpPre + inc;
}
__global__ void k_scan2(int nb) {
    if (threadIdx.x == 0 && blockIdx.x == 0) {
        int run = 0;
        for (int b = 0; b < nb; b++) { int t = g_bsum[b]; g_bsum[b] = run; run += t; }
    }
}
__global__ void k_scan3(int nT) {
    int i = blockIdx.x * blockDim.x + threadIdx.x;
    if (i < nT) g_offs[i] += g_bsum[i >> 10];
}

// ---------------- scatter: CSR pairs + attn output -------------------------------
__global__ void k_scatter(const void* __restrict__ ti, float* __restrict__ attn, int nA) {
    int a = blockIdx.x * blockDim.x + threadIdx.x;
    if (a >= nA) return;
    int t = team_of(ti, a, g_idxflag);
    float w = g_exp[a] / g_denom[t];
    attn[a] = w;
    int p = atomicAdd(&g_cursor[t], 1);
    g_pair[g_offs[t] + p] = make_int2(a, __float_as_int(w));
}

// ---------------- pool: warp per team, 2 agents in flight -------------------------
__global__ void k_pool(const float* __restrict__ A, int nT) {
    int t = (blockIdx.x * blockDim.x + threadIdx.x) >> 5;
    if (t >= nT) return;
    int lane = threadIdx.x & 31;
    int start = g_offs[t];
    int cnt   = g_count[t];
    float4 a0 = make_float4(0.f, 0.f, 0.f, 0.f);
    float4 a1 = make_float4(0.f, 0.f, 0.f, 0.f);
    float4 c0 = make_float4(0.f, 0.f, 0.f, 0.f);
    float4 c1 = make_float4(0.f, 0.f, 0.f, 0.f);
    int i = 0;
    for (; i + 2 <= cnt; i += 2) {
        int2 p0 = g_pair[start + i];
        int2 p1 = g_pair[start + i + 1];
        const float4* r0 = (const float4*)A + (size_t)p0.x * 64;
        const float4* r1 = (const float4*)A + (size_t)p1.x * 64;
        float4 v00 = __ldg(&r0[lane * 2]);
        float4 v01 = __ldg(&r0[lane * 2 + 1]);
        float4 v10 = __ldg(&r1[lane * 2]);
        float4 v11 = __ldg(&r1[lane * 2 + 1]);
        float w0 = __int_as_float(p0.y), w1 = __int_as_float(p1.y);
        a0.x += w0 * v00.x; a0.y += w0 * v00.y; a0.z += w0 * v00.z; a0.w += w0 * v00.w;
        a1.x += w0 * v01.x; a1.y += w0 * v01.y; a1.z += w0 * v01.z; a1.w += w0 * v01.w;
        c0.x += w1 * v10.x; c0.y += w1 * v10.y; c0.z += w1 * v10.z; c0.w += w1 * v10.w;
        c1.x += w1 * v11.x; c1.y += w1 * v11.y; c1.z += w1 * v11.z; c1.w += w1 * v11.w;
    }
    if (i < cnt) {
        int2 p0 = g_pair[start + i];
        const float4* r0 = (const float4*)A + (size_t)p0.x * 64;
        float4 v00 = __ldg(&r0[lane * 2]);
        float4 v01 = __ldg(&r0[lane * 2 + 1]);
        float w0 = __int_as_float(p0.y);
        a0.x += w0 * v00.x; a0.y += w0 * v00.y; a0.z += w0 * v00.z; a0.w += w0 * v00.w;
        a1.x += w0 * v01.x; a1.y += w0 * v01.y; a1.z += w0 * v01.z; a1.w += w0 * v01.w;
    }
    a0.x += c0.x; a0.y += c0.y; a0.z += c0.z; a0.w += c0.w;
    a1.x += c1.x; a1.y += c1.y; a1.z += c1.z; a1.w += c1.w;
    float4* dst = (float4*)g_teamh + (size_t)t * 64;
    dst[lane * 2] = a0; dst[lane * 2 + 1] = a1;
}

// ---------------- GEMM3: out = relu(team_h @ Wo + bo) -----------------------------
__global__ void __launch_bounds__(256, 1)
k_gemm3(const float* __restrict__ Wo, const float* __restrict__ bo,
        float* __restrict__ out, int nT)
{
    extern __shared__ float sm[];
    float* ring = sm;
    float* Hs   = sm + 4 * SLOT_FLOATS;
    float* bos  = Hs + 128 * HS_LD;
    const int tid = threadIdx.x, warp = tid >> 5, lane = tid & 31;
    const int color = blockIdx.x & 1;
    const int nOff  = color << 7;

    if (tid < 128) bos[tid] = bo[nOff + tid];

    wm::fragment<wm::matrix_b, 16, 16, 8, wm::precision::tf32, wm::row_major> bfr[32];
    for (int pass = 0; pass < 2; pass++) {
        __syncthreads();
        for (int i = tid; i < 4096; i += 256) {
            int r = i >> 5, c4 = i & 31;
            float4 v = ((const float4*)Wo)[(pass * 128 + r) * 64 + (nOff >> 2) + c4];
            float* d = &Hs[r * HS_LD + c4 * 4];
            d[0] = wm::__float_to_tf32(v.x); d[1] = wm::__float_to_tf32(v.y);
            d[2] = wm::__float_to_tf32(v.z); d[3] = wm::__float_to_tf32(v.w);
        }
        __syncthreads();
        #pragma unroll
        for (int kk = 0; kk < 16; kk++)
            wm::load_matrix_sync(bfr[pass * 16 + kk], &Hs[(kk * 8) * HS_LD + warp * 16], HS_LD);
    }

    const float* src = g_teamh;
    const int ntiles = (nT + 127) >> 7;
    const int start  = (int)blockIdx.x >> 1;
    const int stride = (int)gridDim.x >> 1;
    int myT = (start < ntiles) ? (ntiles - start + stride - 1) / stride : 0;
    const int totQ = myT * 4;

    auto stage = [&](int q) {
        if (q < totQ) {
            int ti = start + (q >> 2) * stride;
            int c  = q & 3;
            int row0 = ti << 7;
            float* dst = ring + (q & 3) * SLOT_FLOATS;
            for (int i = tid; i < 2048; i += 256) {
                int r = i >> 4, grp = i & 15;
                int g = row0 + r;
                int ok = (g < nT);
                int sz = ok ? 16 : 0;
                const float* s = src + (size_t)(ok ? g : 0) * 256 + c * 64 + grp * 4;
                unsigned da = (unsigned)__cvta_generic_to_shared(&dst[r * CHUNK_LD + grp * 4]);
                asm volatile("cp.async.cg.shared.global [%0], [%1], 16, %2;\n"
                             :: "r"(da), "l"(s), "r"(sz));
            }
        }
        asm volatile("cp.async.commit_group;\n");
    };

    wm::fragment<wm::accumulator, 16, 16, 8, float> acc[8];
    #pragma unroll
    for (int m = 0; m < 8; m++) wm::fill_fragment(acc[m], 0.f);

    stage(0); stage(1); stage(2);
    for (int q = 0; q < totQ; q++) {
        asm volatile("cp.async.wait_group 2;\n");
        __syncthreads();
        float* slot = ring + (q & 3) * SLOT_FLOATS;
        const int kb = (q & 3) * 8;
        #pragma unroll
        for (int k8 = 0; k8 < 8; k8++) {
            #pragma unroll
            for (int m = 0; m < 8; m++) {
                wm::fragment<wm::matrix_a, 16, 16, 8, wm::precision::tf32, wm::row_major> af;
                wm::load_matrix_sync(af, &slot[(m * 16) * CHUNK_LD + k8 * 8], CHUNK_LD);
                wm::mma_sync(acc[m], af, bfr[kb + k8], acc[m]);
            }
        }
        stage(q + 3);
        if ((q & 3) == 3) {
            #pragma unroll
            for (int m = 0; m < 8; m++) {
                wm::store_matrix_sync(&Hs[(m * 16) * HS_LD + warp * 16], acc[m], HS_LD,
                                      wm::mem_row_major);
                wm::fill_fragment(acc[m], 0.f);
            }
            __syncthreads();
            const int row0 = (start + (q >> 2) * stride) << 7;
            #pragma unroll
            for (int rr = 0; rr < 16; rr++) {
                int r = warp * 16 + rr;
                int g = row0 + r;
                if (g < nT) {
                    int c = lane * 4;
                    float4 h = *(const float4*)&Hs[r * HS_LD + c];
                    h.x = fmaxf(h.x + bos[c],     0.f);
                    h.y = fmaxf(h.y + bos[c + 1], 0.f);
                    h.z = fmaxf(h.z + bos[c + 2], 0.f);
                    h.w = fmaxf(h.w + bos[c + 3], 0.f);
                    *(float4*)&out[(size_t)g * 256 + nOff + c] = h;
                }
            }
        }
    }
}

// ---------------- launch -----------------------------------------------------------
extern "C" void kernel_launch(void* const* d_in, const int* in_sizes, int n_in,
                              void* d_out, int out_size)
{
    const float* agent_h  = (const float*)d_in[0];
    const void*  team_idx = d_in[1];
    int wbase = (in_sizes[2] == 256 * 128) ? 2 : 3;
    const float* W1 = (const float*)d_in[wbase + 0];
    const float* b1 = (const float*)d_in[wbase + 1];
    const float* W2 = (const float*)d_in[wbase + 2];
    const float* b2 = (const float*)d_in[wbase + 3];
    const float* Wo = (const float*)d_in[wbase + 4];
    const float* bo = (const float*)d_in[wbase + 5];

    const int nA = in_sizes[0] / 256;
    const int nT = (out_size - nA) / 256;
    float* out  = (float*)d_out;
    float* attn = out + (size_t)nT * 256;

    cudaFuncSetAttribute(k_gemm1, cudaFuncAttributeMaxDynamicSharedMemorySize, SM_BYTES);
    cudaFuncSetAttribute(k_gemm3, cudaFuncAttributeMaxDynamicSharedMemorySize, SM_BYTES);

    const int nb = (nT + 1023) / 1024;

    k_detect<<<1, 32>>>(team_idx, nA, nT);                                  // 1
    k_clearA<<<(nT + 255) / 256, 256>>>(nT);                                // 2
    k_clearB<<<(nT + 255) / 256, 256>>>(nT);                                // 3
    k_gemm1<<<152, 256, SM_BYTES>>>(agent_h, W1, b1, W2, b2, nA);           // 4 (profiled)
    k_accum<<<(nA + 255) / 256, 256>>>(team_idx, nA);                       // 5
    k_scan1<<<nb, 1024>>>(nT);                                              // 6
    k_scan2<<<1, 32>>>(nb);                                                 // 7
    k_scan3<<<(nT + 255) / 256, 256>>>(nT);                                 // 8
    k_scatter<<<(nA + 255) / 256, 256>>>(team_idx, attn, nA);               // 9
    k_pool<<<(nT + 7) / 8, 256>>>(agent_h, nT);                             // 10
    k_gemm3<<<152, 256, SM_BYTES>>>(Wo, bo, out, nT);                       // 11
}

// round 16
// speedup vs baseline: 1.0024x; 1.0024x over previous
#include <cuda_runtime.h>
#include <mma.h>

namespace wm = nvcuda::wmma;

#define MAXA 400000
#define MAXT 100000

// ---------------- device scratch ---------------------------------------------
__device__ float g_exp[MAXA];
__device__ float g_denom[MAXT];
__device__ int   g_count[MAXT];
__device__ int   g_offs[MAXT];
__device__ int   g_cursor[MAXT];
__device__ int2  g_pair[MAXA];
__device__ int   g_bsum[256];
__device__ int   g_idxflag;
__device__ float g_teamh[MAXT * 256];

__device__ __forceinline__ int team_of(const void* ti, int a, int f64) {
    return f64 ? (int)((const long long*)ti)[a] : ((const int*)ti)[a];
}
__device__ __forceinline__ float fast_tanh(float x) {
    float y; asm("tanh.approx.f32 %0, %1;" : "=f"(y) : "f"(x)); return y;
}
__device__ __forceinline__ float fast_exp(float x) {
    float y; asm("ex2.approx.f32 %0, %1;" : "=f"(y) : "f"(x * 1.4426950408889634f));
    return y;
}

// ---------------- smem layout for both GEMMs ----------------------------------
// ring: 4 slots x (128 rows x 68 floats)  = 34816 floats
// Hs:   128 x 132                          = 16896 floats
// bias: 2 x 128
#define CHUNK_LD 68
#define SLOT_FLOATS (128 * CHUNK_LD)
#define HS_LD 132
#define SM_FLOATS (4 * SLOT_FLOATS + 128 * HS_LD + 256)
#define SM_BYTES  (SM_FLOATS * 4)

// ---------------- init kernels -------------------------------------------------
__global__ void k_detect(const void* __restrict__ ti, int nA, int nT) {
    if (blockIdx.x == 0 && threadIdx.x < 32) {
        const long long* p = (const long long*)ti;
        int n = nA < 64 ? nA : 64;
        bool bad = false;
        for (int j = threadIdx.x; j < n; j += 32) {
            long long v = p[j];
            if (v < 0 || v >= (long long)nT) bad = true;
        }
        unsigned m = __ballot_sync(0xffffffffu, bad);
        if (threadIdx.x == 0) g_idxflag = (m == 0) ? 1 : 0;
    }
}
__global__ void k_clearA(int nT) {
    int i = blockIdx.x * blockDim.x + threadIdx.x;
    if (i < nT) { g_denom[i] = 0.f; g_count[i] = 0; }
}
__global__ void k_clearB(int nT) {
    int i = blockIdx.x * blockDim.x + threadIdx.x;
    if (i < nT) g_cursor[i] = 0;
}

// ---------------- GEMM1: g_exp = exp(tanh(A@W1+b1)@W2 + b2) -------------------
__global__ void __launch_bounds__(256, 1)
k_gemm1(const float* __restrict__ A, const float* __restrict__ W1,
        const float* __restrict__ b1, const float* __restrict__ W2,
        const float* __restrict__ b2p, int nA)
{
    extern __shared__ float sm[];
    float* ring = sm;
    float* Hs   = sm + 4 * SLOT_FLOATS;
    float* b1s  = Hs + 128 * HS_LD;
    float* W2s  = b1s + 128;
    const int tid = threadIdx.x, warp = tid >> 5, lane = tid & 31;

    if (tid < 128) { b1s[tid] = b1[tid]; W2s[tid] = W2[tid]; }

    // preload W1 -> register B fragments (two 128-row passes through Hs)
    wm::fragment<wm::matrix_b, 16, 16, 8, wm::precision::tf32, wm::row_major> bfr[32];
    for (int pass = 0; pass < 2; pass++) {
        __syncthreads();
        for (int i = tid; i < 4096; i += 256) {
            int r = i >> 5, c4 = i & 31;
            float4 v = ((const float4*)W1)[pass * 4096 + i];
            float* d = &Hs[r * HS_LD + c4 * 4];
            d[0] = wm::__float_to_tf32(v.x); d[1] = wm::__float_to_tf32(v.y);
            d[2] = wm::__float_to_tf32(v.z); d[3] = wm::__float_to_tf32(v.w);
        }
        __syncthreads();
        #pragma unroll
        for (int kk = 0; kk < 16; kk++)
            wm::load_matrix_sync(bfr[pass * 16 + kk], &Hs[(kk * 8) * HS_LD + warp * 16], HS_LD);
    }
    const float b2 = b2p[0];

    const int ntiles = (nA + 127) >> 7;
    int myT = ((int)blockIdx.x < ntiles)
            ? (ntiles - (int)blockIdx.x + (int)gridDim.x - 1) / (int)gridDim.x : 0;
    const int totQ = myT * 4;

    auto stage = [&](int q) {
        if (q < totQ) {
            int ti = (int)blockIdx.x + (q >> 2) * (int)gridDim.x;
            int c  = q & 3;
            int row0 = ti << 7;
            float* dst = ring + (q & 3) * SLOT_FLOATS;
            for (int i = tid; i < 2048; i += 256) {
                int r = i >> 4, grp = i & 15;
                int g = row0 + r;
                int ok = (g < nA);
                int sz = ok ? 16 : 0;
                const float* s = A + (size_t)(ok ? g : 0) * 256 + c * 64 + grp * 4;
                unsigned da = (unsigned)__cvta_generic_to_shared(&dst[r * CHUNK_LD + grp * 4]);
                asm volatile("cp.async.cg.shared.global [%0], [%1], 16, %2;\n"
                             :: "r"(da), "l"(s), "r"(sz));
            }
        }
        asm volatile("cp.async.commit_group;\n");
    };

    wm::fragment<wm::accumulator, 16, 16, 8, float> acc[8];
    #pragma unroll
    for (int m = 0; m < 8; m++) wm::fill_fragment(acc[m], 0.f);

    stage(0); stage(1); stage(2);
    for (int q = 0; q < totQ; q++) {
        asm volatile("cp.async.wait_group 2;\n");
        __syncthreads();
        float* slot = ring + (q & 3) * SLOT_FLOATS;
        const int kb = (q & 3) * 8;
        #pragma unroll
        for (int k8 = 0; k8 < 8; k8++) {
            #pragma unroll
            for (int m = 0; m < 8; m++) {
                wm::fragment<wm::matrix_a, 16, 16, 8, wm::precision::tf32, wm::row_major> af;
                wm::load_matrix_sync(af, &slot[(m * 16) * CHUNK_LD + k8 * 8], CHUNK_LD);
                wm::mma_sync(acc[m], af, bfr[kb + k8], acc[m]);
            }
        }
        stage(q + 3);
        if ((q & 3) == 3) {
            #pragma unroll
            for (int m = 0; m < 8; m++) {
                wm::store_matrix_sync(&Hs[(m * 16) * HS_LD + warp * 16], acc[m], HS_LD,
                                      wm::mem_row_major);
                wm::fill_fragment(acc[m], 0.f);
            }
            __syncthreads();
            const int row0 = ((int)blockIdx.x + (q >> 2) * (int)gridDim.x) << 7;
            #pragma unroll
            for (int rr = 0; rr < 16; rr++) {
                int r = warp * 16 + rr;
                int c = lane * 4;
                float4 h = *(const float4*)&Hs[r * HS_LD + c];
                float s = fast_tanh(h.x + b1s[c])     * W2s[c]
                        + fast_tanh(h.y + b1s[c + 1]) * W2s[c + 1]
                        + fast_tanh(h.z + b1s[c + 2]) * W2s[c + 2]
                        + fast_tanh(h.w + b1s[c + 3]) * W2s[c + 3];
                #pragma unroll
                for (int o = 16; o > 0; o >>= 1) s += __shfl_xor_sync(0xffffffffu, s, o);
                int g = row0 + r;
                if (lane == 0 && g < nA) g_exp[g] = fast_exp(s + b2);
            }
        }
    }
}

// ---------------- denom + count (separate: off the GEMM critical path) --------
__global__ void k_accum(const void* __restrict__ ti, int nA) {
    int a = blockIdx.x * blockDim.x + threadIdx.x;
    if (a >= nA) return;
    int t = team_of(ti, a, g_idxflag);
    atomicAdd(&g_denom[t], g_exp[a]);
    atomicAdd(&g_count[t], 1);
}

// ---------------- scan (counts -> offsets) --------------------------------------
__global__ void k_scan1(int nT) {
    __shared__ int ws[32];
    int i = blockIdx.x * 1024 + threadIdx.x;
    int lane = threadIdx.x & 31, wid = threadIdx.x >> 5;
    int v = (i < nT) ? g_count[i] : 0;
    int inc = v;
    #pragma unroll
    for (int o = 1; o < 32; o <<= 1) {
        int n = __shfl_up_sync(0xffffffffu, inc, o);
        if (lane >= o) inc += n;
    }
    if (lane == 31) ws[wid] = inc;
    __syncthreads();
    if (wid == 0) {
        int tt = ws[lane];
        #pragma unroll
        for (int o = 1; o < 32; o <<= 1) {
            int n = __shfl_up_sync(0xffffffffu, tt, o);
            if (lane >= o) tt += n;
        }
        ws[lane] = tt;
    }
    __syncthreads();
    int warpPre = wid ? ws[wid - 1] : 0;
    if (i < nT) g_offs[i] = warpPre + inc - v;
    if (threadIdx.x == 1023) g_bsum[blockIdx.x] = warpPre + inc;
}
__global__ void k_scan2(int nb) {
    if (threadIdx.x == 0 && blockIdx.x == 0) {
        int run = 0;
        for (int b = 0; b < nb; b++) { int t = g_bsum[b]; g_bsum[b] = run; run += t; }
    }
}
__global__ void k_scan3(int nT) {
    int i = blockIdx.x * blockDim.x + threadIdx.x;
    if (i < nT) g_offs[i] += g_bsum[i >> 10];
}

// ---------------- scatter: CSR pairs + attn output -------------------------------
__global__ void k_scatter(const void* __restrict__ ti, float* __restrict__ attn, int nA) {
    int a = blockIdx.x * blockDim.x + threadIdx.x;
    if (a >= nA) return;
    int t = team_of(ti, a, g_idxflag);
    float w = g_exp[a] / g_denom[t];
    attn[a] = w;
    int p = atomicAdd(&g_cursor[t], 1);
    g_pair[g_offs[t] + p] = make_int2(a, __float_as_int(w));
}

// ---------------- pool: warp per team, 2 agents in flight -------------------------
__global__ void k_pool(const float* __restrict__ A, int nT) {
    int t = (blockIdx.x * blockDim.x + threadIdx.x) >> 5;
    if (t >= nT) return;
    int lane = threadIdx.x & 31;
    int start = g_offs[t];
    int cnt   = g_count[t];
    float4 a0 = make_float4(0.f, 0.f, 0.f, 0.f);
    float4 a1 = make_float4(0.f, 0.f, 0.f, 0.f);
    float4 c0 = make_float4(0.f, 0.f, 0.f, 0.f);
    float4 c1 = make_float4(0.f, 0.f, 0.f, 0.f);
    int i = 0;
    for (; i + 2 <= cnt; i += 2) {
        int2 p0 = g_pair[start + i];
        int2 p1 = g_pair[start + i + 1];
        const float4* r0 = (const float4*)A + (size_t)p0.x * 64;
        const float4* r1 = (const float4*)A + (size_t)p1.x * 64;
        float4 v00 = __ldg(&r0[lane * 2]);
        float4 v01 = __ldg(&r0[lane * 2 + 1]);
        float4 v10 = __ldg(&r1[lane * 2]);
        float4 v11 = __ldg(&r1[lane * 2 + 1]);
        float w0 = __int_as_float(p0.y), w1 = __int_as_float(p1.y);
        a0.x += w0 * v00.x; a0.y += w0 * v00.y; a0.z += w0 * v00.z; a0.w += w0 * v00.w;
        a1.x += w0 * v01.x; a1.y += w0 * v01.y; a1.z += w0 * v01.z; a1.w += w0 * v01.w;
        c0.x += w1 * v10.x; c0.y += w1 * v10.y; c0.z += w1 * v10.z; c0.w += w1 * v10.w;
        c1.x += w1 * v11.x; c1.y += w1 * v11.y; c1.z += w1 * v11.z; c1.w += w1 * v11.w;
    }
    if (i < cnt) {
        int2 p0 = g_pair[start + i];
        const float4* r0 = (const float4*)A + (size_t)p0.x * 64;
        float4 v00 = __ldg(&r0[lane * 2]);
        float4 v01 = __ldg(&r0[lane * 2 + 1]);
        float w0 = __int_as_float(p0.y);
        a0.x += w0 * v00.x; a0.y += w0 * v00.y; a0.z += w0 * v00.z; a0.w += w0 * v00.w;
        a1.x += w0 * v01.x; a1.y += w0 * v01.y; a1.z += w0 * v01.z; a1.w += w0 * v01.w;
    }
    a0.x += c0.x; a0.y += c0.y; a0.z += c0.z; a0.w += c0.w;
    a1.x += c1.x; a1.y += c1.y; a1.z += c1.z; a1.w += c1.w;
    float4* dst = (float4*)g_teamh + (size_t)t * 64;
    dst[lane * 2] = a0; dst[lane * 2 + 1] = a1;
}

// ---------------- GEMM3: out = relu(team_h @ Wo + bo) -----------------------------
__global__ void __launch_bounds__(256, 1)
k_gemm3(const float* __restrict__ Wo, const float* __restrict__ bo,
        float* __restrict__ out, int nT)
{
    extern __shared__ float sm[];
    float* ring = sm;
    float* Hs   = sm + 4 * SLOT_FLOATS;
    float* bos  = Hs + 128 * HS_LD;
    const int tid = threadIdx.x, warp = tid >> 5, lane = tid & 31;
    const int color = blockIdx.x & 1;
    const int nOff  = color << 7;

    if (tid < 128) bos[tid] = bo[nOff + tid];

    wm::fragment<wm::matrix_b, 16, 16, 8, wm::precision::tf32, wm::row_major> bfr[32];
    for (int pass = 0; pass < 2; pass++) {
        __syncthreads();
        for (int i = tid; i < 4096; i += 256) {
            int r = i >> 5, c4 = i & 31;
            float4 v = ((const float4*)Wo)[(pass * 128 + r) * 64 + (nOff >> 2) + c4];
            float* d = &Hs[r * HS_LD + c4 * 4];
            d[0] = wm::__float_to_tf32(v.x); d[1] = wm::__float_to_tf32(v.y);
            d[2] = wm::__float_to_tf32(v.z); d[3] = wm::__float_to_tf32(v.w);
        }
        __syncthreads();
        #pragma unroll
        for (int kk = 0; kk < 16; kk++)
            wm::load_matrix_sync(bfr[pass * 16 + kk], &Hs[(kk * 8) * HS_LD + warp * 16], HS_LD);
    }

    const float* src = g_teamh;
    const int ntiles = (nT + 127) >> 7;
    const int start  = (int)blockIdx.x >> 1;
    const int stride = (int)gridDim.x >> 1;
    int myT = (start < ntiles) ? (ntiles - start + stride - 1) / stride : 0;
    const int totQ = myT * 4;

    auto stage = [&](int q) {
        if (q < totQ) {
            int ti = start + (q >> 2) * stride;
            int c  = q & 3;
            int row0 = ti << 7;
            float* dst = ring + (q & 3) * SLOT_FLOATS;
            for (int i = tid; i < 2048; i += 256) {
                int r = i >> 4, grp = i & 15;
                int g = row0 + r;
                int ok = (g < nT);
                int sz = ok ? 16 : 0;
                const float* s = src + (size_t)(ok ? g : 0) * 256 + c * 64 + grp * 4;
                unsigned da = (unsigned)__cvta_generic_to_shared(&dst[r * CHUNK_LD + grp * 4]);
                asm volatile("cp.async.cg.shared.global [%0], [%1], 16, %2;\n"
                             :: "r"(da), "l"(s), "r"(sz));
            }
        }
        asm volatile("cp.async.commit_group;\n");
    };

    wm::fragment<wm::accumulator, 16, 16, 8, float> acc[8];
    #pragma unroll
    for (int m = 0; m < 8; m++) wm::fill_fragment(acc[m], 0.f);

    stage(0); stage(1); stage(2);
    for (int q = 0; q < totQ; q++) {
        asm volatile("cp.async.wait_group 2;\n");
        __syncthreads();
        float* slot = ring + (q & 3) * SLOT_FLOATS;
        const int kb = (q & 3) * 8;
        #pragma unroll
        for (int k8 = 0; k8 < 8; k8++) {
            #pragma unroll
            for (int m = 0; m < 8; m++) {
                wm::fragment<wm::matrix_a, 16, 16, 8, wm::precision::tf32, wm::row_major> af;
                wm::load_matrix_sync(af, &slot[(m * 16) * CHUNK_LD + k8 * 8], CHUNK_LD);
                wm::mma_sync(acc[m], af, bfr[kb + k8], acc[m]);
            }
        }
        stage(q + 3);
        if ((q & 3) == 3) {
            #pragma unroll
            for (int m = 0; m < 8; m++) {
                wm::store_matrix_sync(&Hs[(m * 16) * HS_LD + warp * 16], acc[m], HS_LD,
                                      wm::mem_row_major);
                wm::fill_fragment(acc[m], 0.f);
            }
            __syncthreads();
            const int row0 = (start + (q >> 2) * stride) << 7;
            #pragma unroll
            for (int rr = 0; rr < 16; rr++) {
                int r = warp * 16 + rr;
                int g = row0 + r;
                if (g < nT) {
                    int c = lane * 4;
                    float4 h = *(const float4*)&Hs[r * HS_LD + c];
                    h.x = fmaxf(h.x + bos[c],     0.f);
                    h.y = fmaxf(h.y + bos[c + 1], 0.f);
                    h.z = fmaxf(h.z + bos[c + 2], 0.f);
                    h.w = fmaxf(h.w + bos[c + 3], 0.f);
                    *(float4*)&out[(size_t)g * 256 + nOff + c] = h;
                }
            }
        }
    }
}

// ---------------- launch -----------------------------------------------------------
extern "C" void kernel_launch(void* const* d_in, const int* in_sizes, int n_in,
                              void* d_out, int out_size)
{
    const float* agent_h  = (const float*)d_in[0];
    const void*  team_idx = d_in[1];
    int wbase = (in_sizes[2] == 256 * 128) ? 2 : 3;
    const float* W1 = (const float*)d_in[wbase + 0];
    const float* b1 = (const float*)d_in[wbase + 1];
    const float* W2 = (const float*)d_in[wbase + 2];
    const float* b2 = (const float*)d_in[wbase + 3];
    const float* Wo = (const float*)d_in[wbase + 4];
    const float* bo = (const float*)d_in[wbase + 5];

    const int nA = in_sizes[0] / 256;
    const int nT = (out_size - nA) / 256;
    float* out  = (float*)d_out;
    float* attn = out + (size_t)nT * 256;

    cudaFuncSetAttribute(k_gemm1, cudaFuncAttributeMaxDynamicSharedMemorySize, SM_BYTES);
    cudaFuncSetAttribute(k_gemm3, cudaFuncAttributeMaxDynamicSharedMemorySize, SM_BYTES);

    const int nb = (nT + 1023) / 1024;

    k_detect<<<1, 32>>>(team_idx, nA, nT);                                  // 1
    k_clearA<<<(nT + 255) / 256, 256>>>(nT);                                // 2
    k_clearB<<<(nT + 255) / 256, 256>>>(nT);                                // 3
    k_gemm1<<<152, 256, SM_BYTES>>>(agent_h, W1, b1, W2, b2, nA);           // 4 (profiled)
    k_accum<<<(nA + 255) / 256, 256>>>(team_idx, nA);                       // 5
    k_scan1<<<nb, 1024>>>(nT);                                              // 6
    k_scan2<<<1, 32>>>(nb);                                                 // 7
    k_scan3<<<(nT + 255) / 256, 256>>>(nT);                                 // 8
    k_scatter<<<(nA + 255) / 256, 256>>>(team_idx, attn, nA);               // 9
    k_pool<<<(nT + 7) / 8, 256>>>(agent_h, nT);                             // 10
    k_gemm3<<<152, 256, SM_BYTES>>>(Wo, bo, out, nT);                       // 11
}